// round 11
// baseline (speedup 1.0000x reference)
#include <cuda_runtime.h>
#include <cuda_fp16.h>
#include <math.h>
#include <stdint.h>

// Problem constants
#define Bb 2
#define Hh 8
#define Ss 2048
#define Dd 512
#define Mrows (Bb * Ss)          // 4096
#define CONCAT_K (Hh * Dd)       // 4096

// ---------------------------------------------------------------------------
// Scratch (device globals; allocation is forbidden)
// ---------------------------------------------------------------------------
__device__ __half gx16[(size_t)Mrows * Dd];                 // 4 MB   [m][d]
__device__ __half gWqt16[(size_t)Hh * Dd * Dd];             // 4 MB   [h][e][d]
__device__ __half gWkt16[(size_t)Hh * Dd * Dd];
__device__ __half gWvt16[(size_t)Hh * Dd * Dd];
__device__ __half gWot16[(size_t)Dd * CONCAT_K];            // 4 MB   [e][hd]
__device__ __half gQ16[(size_t)Hh * Mrows * Dd];            // 32 MB  [h][m][e]
__device__ __half gK16[(size_t)Hh * Mrows * Dd];            // 32 MB
__device__ __half gV16[(size_t)Hh * Mrows * Dd];            // 32 MB  [h][m][e]
__device__ __half gVt16[(size_t)Hh * Dd * Mrows];           // 32 MB  [h][e][m]
__device__ __half gS16[(size_t)Bb * Hh * Ss * Ss];          // 128 MB [z][q][k]  scores -> (in-place) softmax P
__device__ __half gC16[(size_t)Mrows * CONCAT_K];           // 32 MB  [m][h*D+e]

// ---------------------------------------------------------------------------
// helpers
// ---------------------------------------------------------------------------
__device__ __forceinline__ uint32_t smem_u32(const void* p) {
    uint32_t a;
    asm("{ .reg .u64 t; cvta.to.shared.u64 t, %1; cvt.u32.u64 %0, t; }" : "=r"(a) : "l"(p));
    return a;
}
#define CP16(dst, src) asm volatile("cp.async.cg.shared.global [%0], [%1], 16;" :: "r"(dst), "l"(src))
#define CP_COMMIT()    asm volatile("cp.async.commit_group;" ::: "memory")
#define CP_WAIT1()     asm volatile("cp.async.wait_group 1;" ::: "memory")

__device__ __forceinline__ uint32_t lds32(uint32_t a) {
    uint32_t v;
    asm volatile("ld.shared.b32 %0, [%1];" : "=r"(v) : "r"(a));
    return v;
}

__device__ __forceinline__ void mma16816(float* c, const uint32_t* a, const uint32_t* b) {
    asm volatile(
        "mma.sync.aligned.m16n8k16.row.col.f32.f16.f16.f32 "
        "{%0,%1,%2,%3},{%4,%5,%6,%7},{%8,%9},{%0,%1,%2,%3};\n"
        : "+f"(c[0]), "+f"(c[1]), "+f"(c[2]), "+f"(c[3])
        : "r"(a[0]), "r"(a[1]), "r"(a[2]), "r"(a[3]), "r"(b[0]), "r"(b[1]));
}

// ---------------------------------------------------------------------------
// fp16 GEMM: C = alpha * A @ B^T (+ bias) (+ resid)
// A: [M,K] fp16 K-major (lda halves), B: [N,K] fp16 K-major (ldb halves).
// CTA tile 128x64, K-chunk 32, 3-stage cp.async pipeline, 128 threads,
// 4 warps (2x2), warp tile 64x32, mma m16n8k16, scalar-LDS fragments
// (identical per-warp stream to the proven 814us kernel; only CTA shape
// changed 256thr/128x128 -> 128thr/128x64 for 4 CTAs/SM barrier decoupling).
//
// MODE: 0 = merged QKV proj (z = which*8+h, half out),
//       1 = QK^T (z=b*8+h, HALF out, alpha),
//       2 = P@V (z=b*8+h, half out into concat),
//       3 = out proj (f32 + bias + resid)
// ---------------------------------------------------------------------------
#define ROW_B 80u
#define A_ST_BYTES (128u * ROW_B)        // 10240
#define B_ST_BYTES (64u * ROW_B)         // 5120
#define STAGE_BYTES (A_ST_BYTES + B_ST_BYTES)   // 15360
#define HG_SMEM (3 * 15360)              // 46080

template <int MODE>
__global__ __launch_bounds__(128, 4)
void hgemm(const __half* __restrict__ A0, const __half* __restrict__ B0,
           const __half* __restrict__ B1v, const __half* __restrict__ B2v,
           void* __restrict__ C0, void* __restrict__ C1v, void* __restrict__ C2v,
           const float* __restrict__ bias0, const float* __restrict__ bias1,
           const float* __restrict__ bias2, const float* __restrict__ resid0,
           int K, int lda, int ldb, int ldc, float alpha)
{
    extern __shared__ char sm[];
    const uint32_t sbase = smem_u32(sm);

    const int tid = threadIdx.x;
    const int lane = tid & 31;
    const int wid = tid >> 5;        // 0..3
    const int g = lane >> 2;
    const int tig = lane & 3;
    const int warp_m = wid >> 1;     // 0..1  (64-row slabs)
    const int warp_n = wid & 1;      // 0..1  (32-col slabs)
    const int bx = blockIdx.x, by = blockIdx.y;

    const __half* A = A0;
    const __half* B = B0;
    const float* bias = bias0;
    float* Cf = (float*)C0;
    __half* Ch = (__half*)C0;
    {
        const int z = blockIdx.z;
        if (MODE == 0) {
            const int which = z >> 3, h = z & 7;
            const __half* W = (which == 0) ? B0 : ((which == 1) ? B1v : B2v);
            B = W + (size_t)h * Dd * Dd;
            __half* Co = (__half*)((which == 0) ? C0 : ((which == 1) ? C1v : C2v));
            Ch = Co + (size_t)h * Mrows * Dd;
            const float* bs = (which == 0) ? bias0 : ((which == 1) ? bias1 : bias2);
            bias = bs + (size_t)h * Dd;
        } else if (MODE == 1) {
            const int h = z & 7, b = z >> 3;
            const size_t off = ((size_t)h * Mrows + (size_t)b * Ss) * Dd;
            A += off; B += off;
            Ch += (size_t)z * Ss * Ss;
        } else if (MODE == 2) {
            const int h = z & 7, b = z >> 3;
            A += (size_t)z * Ss * Ss;
            B += (size_t)h * Dd * Mrows + (size_t)b * Ss;
            Ch += (size_t)b * Ss * CONCAT_K + (size_t)h * Dd;
        }
    }

    const __half* Arow = A + (size_t)(by * 128) * lda;
    const __half* Brow = B + (size_t)(bx * 64) * ldb;

    // loaders: A tile 128 rows x 4 float4 = 512 CP16 (4/thread),
    //          B tile  64 rows x 4 float4 = 256 CP16 (2/thread)
    auto issue = [&](int c, int st) {
        const __half* Ac = Arow + c * 32;
        const __half* Bc = Brow + c * 32;
        const uint32_t sA = sbase + (uint32_t)st * STAGE_BYTES;
        const uint32_t sB = sA + A_ST_BYTES;
#pragma unroll
        for (int t = 0; t < 4; t++) {
            const int i = tid + t * 128;
            const int r = i >> 2, f = i & 3;
            CP16(sA + (uint32_t)r * ROW_B + f * 16, Ac + (size_t)r * lda + f * 8);
        }
#pragma unroll
        for (int t = 0; t < 2; t++) {
            const int i = tid + t * 128;
            const int r = i >> 2, f = i & 3;
            CP16(sB + (uint32_t)r * ROW_B + f * 16, Bc + (size_t)r * ldb + f * 8);
        }
    };

    float acc[4][4][4];
#pragma unroll
    for (int mi = 0; mi < 4; mi++)
#pragma unroll
        for (int ni = 0; ni < 4; ni++)
#pragma unroll
            for (int r = 0; r < 4; r++) acc[mi][ni][r] = 0.0f;

    const int nchunks = K >> 5;

    issue(0, 0); CP_COMMIT();
    issue(1, 1); CP_COMMIT();

    for (int c = 0; c < nchunks; c++) {
        CP_WAIT1();
        __syncthreads();

        const int st = c % 3;
        const uint32_t baseA = sbase + (uint32_t)st * STAGE_BYTES;
        const uint32_t baseB = baseA + A_ST_BYTES;
#pragma unroll
        for (int ks = 0; ks < 2; ks++) {
            const uint32_t kb = (uint32_t)(ks * 8 + tig) * 4;
            uint32_t a[4][4], b[4][2];
#pragma unroll
            for (int mi = 0; mi < 4; mi++) {
                const uint32_t ra = baseA + (uint32_t)(warp_m * 64 + mi * 16 + g) * ROW_B + kb;
                a[mi][0] = lds32(ra);
                a[mi][1] = lds32(ra + 8 * ROW_B);
                a[mi][2] = lds32(ra + 16);
                a[mi][3] = lds32(ra + 8 * ROW_B + 16);
            }
#pragma unroll
            for (int ni = 0; ni < 4; ni++) {
                const uint32_t rb = baseB + (uint32_t)(warp_n * 32 + ni * 8 + g) * ROW_B + kb;
                b[ni][0] = lds32(rb);
                b[ni][1] = lds32(rb + 16);
            }
#pragma unroll
            for (int mi = 0; mi < 4; mi++)
#pragma unroll
                for (int ni = 0; ni < 4; ni++)
                    mma16816(acc[mi][ni], a[mi], b[ni]);
        }

        if (c + 2 < nchunks) issue(c + 2, (c + 2) % 3);
        CP_COMMIT();
    }

    // epilogue
#pragma unroll
    for (int mi = 0; mi < 4; mi++) {
        const int row0 = by * 128 + warp_m * 64 + mi * 16 + g;
#pragma unroll
        for (int ni = 0; ni < 4; ni++) {
            const int col = bx * 64 + warp_n * 32 + ni * 8 + 2 * tig;
            float2 v0, v1;
            v0.x = acc[mi][ni][0] * alpha; v0.y = acc[mi][ni][1] * alpha;
            v1.x = acc[mi][ni][2] * alpha; v1.y = acc[mi][ni][3] * alpha;
            if (MODE == 0 || MODE == 3) {
                const float b0 = bias[col], b1 = bias[col + 1];
                v0.x += b0; v0.y += b1;
                v1.x += b0; v1.y += b1;
            }
            if (MODE == 3) {
                const float2 r0 = *(const float2*)&resid0[(size_t)row0 * ldc + col];
                const float2 r1 = *(const float2*)&resid0[(size_t)(row0 + 8) * ldc + col];
                v0.x += r0.x; v0.y += r0.y;
                v1.x += r1.x; v1.y += r1.y;
            }
            if (MODE == 3) {
                *(float2*)&Cf[(size_t)row0 * ldc + col] = v0;
                *(float2*)&Cf[(size_t)(row0 + 8) * ldc + col] = v1;
            } else {
                *(__half2*)&Ch[(size_t)row0 * ldc + col] = __floats2half2_rn(v0.x, v0.y);
                *(__half2*)&Ch[(size_t)(row0 + 8) * ldc + col] = __floats2half2_rn(v1.x, v1.y);
            }
        }
    }
}

// ---------------------------------------------------------------------------
// fp32 -> fp16 elementwise (float4 granularity)
// ---------------------------------------------------------------------------
__global__ __launch_bounds__(256)
void cvt_half(const float* __restrict__ in, __half* __restrict__ out)
{
    const size_t i = (size_t)blockIdx.x * 256 + threadIdx.x;
    const float4 v = ((const float4*)in)[i];
    ((__half2*)out)[2 * i]     = __floats2half2_rn(v.x, v.y);
    ((__half2*)out)[2 * i + 1] = __floats2half2_rn(v.z, v.w);
}

// ---------------------------------------------------------------------------
// merged fp32 [z][512][512] -> fp16 transposed, 3 weight tensors (z = which*8+h)
// ---------------------------------------------------------------------------
__global__ __launch_bounds__(256)
void cvtT3(const float* __restrict__ q, const float* __restrict__ k,
           const float* __restrict__ v,
           __half* __restrict__ qo, __half* __restrict__ ko, __half* __restrict__ vo)
{
    __shared__ float t[32][33];
    const int which = blockIdx.z >> 3, h = blockIdx.z & 7;
    const float* in = ((which == 0) ? q : (which == 1) ? k : v) + (size_t)h * Dd * Dd;
    __half* out = ((which == 0) ? qo : (which == 1) ? ko : vo) + (size_t)h * Dd * Dd;
    const int c0 = blockIdx.x * 32, r0 = blockIdx.y * 32;
    const int tx = threadIdx.x & 31, ty = threadIdx.x >> 5;
#pragma unroll
    for (int i = 0; i < 32; i += 8)
        t[ty + i][tx] = in[(size_t)(r0 + ty + i) * Dd + c0 + tx];
    __syncthreads();
#pragma unroll
    for (int i = 0; i < 32; i += 8)
        out[(size_t)(c0 + ty + i) * Dd + r0 + tx] = __float2half(t[tx][ty + i]);
}

// ---------------------------------------------------------------------------
// fp32 [z][R][C] -> fp16 transposed [z][C][R]
// ---------------------------------------------------------------------------
__global__ __launch_bounds__(256)
void cvtT(const float* __restrict__ in, __half* __restrict__ out, int R, int C)
{
    __shared__ float t[32][33];
    in  += (size_t)blockIdx.z * R * C;
    out += (size_t)blockIdx.z * R * C;
    const int c0 = blockIdx.x * 32, r0 = blockIdx.y * 32;
    const int tx = threadIdx.x & 31, ty = threadIdx.x >> 5;
#pragma unroll
    for (int i = 0; i < 32; i += 8)
        t[ty + i][tx] = in[(size_t)(r0 + ty + i) * C + c0 + tx];
    __syncthreads();
#pragma unroll
    for (int i = 0; i < 32; i += 8)
        out[(size_t)(c0 + ty + i) * R + r0 + tx] = __float2half(t[tx][ty + i]);
}

// ---------------------------------------------------------------------------
// fp16 [z][R][C] -> fp16 transposed [z][C][R]
// ---------------------------------------------------------------------------
__global__ __launch_bounds__(256)
void transpose16(const __half* __restrict__ in, __half* __restrict__ out, int R, int C)
{
    __shared__ __half t[32][34];
    in  += (size_t)blockIdx.z * R * C;
    out += (size_t)blockIdx.z * R * C;
    const int c0 = blockIdx.x * 32, r0 = blockIdx.y * 32;
    const int tx = threadIdx.x & 31, ty = threadIdx.x >> 5;
#pragma unroll
    for (int i = 0; i < 32; i += 8)
        t[ty + i][tx] = in[(size_t)(r0 + ty + i) * C + c0 + tx];
    __syncthreads();
#pragma unroll
    for (int i = 0; i < 32; i += 8)
        out[(size_t)(c0 + ty + i) * R + r0 + tx] = t[tx][ty + i];
}

// ---------------------------------------------------------------------------
// Row softmax, fp16 in -> fp16 out, IN PLACE.
// ---------------------------------------------------------------------------
__global__ __launch_bounds__(256)
void softmax16_kernel(__half* __restrict__ S)
{
    __shared__ float red[256];
    __half* p = S + (size_t)blockIdx.x * Ss;
    const int t = threadIdx.x;

    uint4 raw = ((const uint4*)p)[t];
    const __half2* hp = (const __half2*)&raw;
    float2 f[4];
#pragma unroll
    for (int i = 0; i < 4; i++) f[i] = __half22float2(hp[i]);

    float m = f[0].x;
#pragma unroll
    for (int i = 0; i < 4; i++) m = fmaxf(m, fmaxf(f[i].x, f[i].y));
    red[t] = m;
    __syncthreads();
    for (int s = 128; s > 0; s >>= 1) {
        if (t < s) red[t] = fmaxf(red[t], red[t + s]);
        __syncthreads();
    }
    m = red[0];
    __syncthreads();

    float sum = 0.0f;
#pragma unroll
    for (int i = 0; i < 4; i++) {
        f[i].x = expf(f[i].x - m); f[i].y = expf(f[i].y - m);
        sum += f[i].x + f[i].y;
    }
    red[t] = sum;
    __syncthreads();
    for (int s = 128; s > 0; s >>= 1) {
        if (t < s) red[t] += red[t + s];
        __syncthreads();
    }
    const float inv = 1.0f / red[0];

    uint4 outw;
    __half2* op = (__half2*)&outw;
#pragma unroll
    for (int i = 0; i < 4; i++)
        op[i] = __floats2half2_rn(f[i].x * inv, f[i].y * inv);
    ((uint4*)p)[t] = outw;
}

// ---------------------------------------------------------------------------
extern "C" void kernel_launch(void* const* d_in, const int* in_sizes, int n_in,
                              void* d_out, int out_size)
{
    const float* x  = (const float*)d_in[0];
    const float* Wq = (const float*)d_in[1];
    const float* Wk = (const float*)d_in[2];
    const float* Wv = (const float*)d_in[3];
    const float* bq = (const float*)d_in[4];
    const float* bk = (const float*)d_in[5];
    const float* bv = (const float*)d_in[6];
    const float* Wo = (const float*)d_in[7];
    const float* bo = (const float*)d_in[8];
    float* out = (float*)d_out;

    __half *px16, *pWqt, *pWkt, *pWvt, *pWot, *pQ, *pK, *pV, *pVt, *pS, *pC;
    cudaGetSymbolAddress((void**)&px16, gx16);
    cudaGetSymbolAddress((void**)&pWqt, gWqt16);
    cudaGetSymbolAddress((void**)&pWkt, gWkt16);
    cudaGetSymbolAddress((void**)&pWvt, gWvt16);
    cudaGetSymbolAddress((void**)&pWot, gWot16);
    cudaGetSymbolAddress((void**)&pQ, gQ16);
    cudaGetSymbolAddress((void**)&pK, gK16);
    cudaGetSymbolAddress((void**)&pV, gV16);
    cudaGetSymbolAddress((void**)&pVt, gVt16);
    cudaGetSymbolAddress((void**)&pS, gS16);
    cudaGetSymbolAddress((void**)&pC, gC16);

    cudaFuncSetAttribute((const void*)hgemm<0>, cudaFuncAttributeMaxDynamicSharedMemorySize, HG_SMEM);
    cudaFuncSetAttribute((const void*)hgemm<1>, cudaFuncAttributeMaxDynamicSharedMemorySize, HG_SMEM);
    cudaFuncSetAttribute((const void*)hgemm<2>, cudaFuncAttributeMaxDynamicSharedMemorySize, HG_SMEM);
    cudaFuncSetAttribute((const void*)hgemm<3>, cudaFuncAttributeMaxDynamicSharedMemorySize, HG_SMEM);

    const float scale = 0.044194173824159216f;  // 1/sqrt(512)
    const dim3 blk(128);

    // 0) convert inputs to fp16 K-major operands
    cvt_half<<<Mrows * Dd / 1024, 256>>>(x, px16);
    cvtT3<<<dim3(16, 16, 24), 256>>>(Wq, Wk, Wv, pWqt, pWkt, pWvt);
    cvtT<<<dim3(16, 128, 1), 256>>>(Wo, pWot, CONCAT_K, Dd);

    // 1) merged QKV projections: [4096,512] = x16 @ W^T(h) per (which, h)
    hgemm<0><<<dim3(8, 32, 24), blk, HG_SMEM>>>(px16, pWqt, pWkt, pWvt,
                                                pQ, pK, pV, bq, bk, bv, nullptr,
                                                Dd, Dd, Dd, Dd, 1.0f);

    // 1b) V -> transposed [h][e][m]
    transpose16<<<dim3(16, 128, Hh), 256>>>(pV, pVt, Mrows, Dd);

    // 2) scores = scale * Q @ K^T, fp16 out
    hgemm<1><<<dim3(32, 16, Bb * Hh), blk, HG_SMEM>>>(pQ, pK, nullptr, nullptr,
                                                      pS, nullptr, nullptr,
                                                      nullptr, nullptr, nullptr, nullptr,
                                                      Dd, Dd, Dd, Ss, scale);

    // 3) softmax in place (fp16)
    softmax16_kernel<<<Bb * Hh * Ss, 256>>>(pS);

    // 4) O = P @ V -> fp16 concat layout [m][h*512+e]
    hgemm<2><<<dim3(8, 16, Bb * Hh), blk, HG_SMEM>>>(pS, pVt, nullptr, nullptr,
                                                     pC, nullptr, nullptr,
                                                     nullptr, nullptr, nullptr, nullptr,
                                                     Ss, Ss, Mrows, CONCAT_K, 1.0f);

    // 5) out = concat @ Wo^T + bo + x, fp32
    hgemm<3><<<dim3(8, 32, 1), blk, HG_SMEM>>>(pC, pWot, nullptr, nullptr,
                                               out, nullptr, nullptr,
                                               bo, nullptr, nullptr, x,
                                               CONCAT_K, CONCAT_K, CONCAT_K, Dd, 1.0f);
}

// round 12
// speedup vs baseline: 1.7155x; 1.7155x over previous
#include <cuda_runtime.h>
#include <cuda_fp16.h>
#include <math.h>
#include <stdint.h>

// Problem constants
#define Bb 2
#define Hh 8
#define Ss 2048
#define Dd 512
#define Mrows (Bb * Ss)          // 4096
#define CONCAT_K (Hh * Dd)       // 4096

// ---------------------------------------------------------------------------
// Scratch (device globals; allocation is forbidden)
// ---------------------------------------------------------------------------
__device__ __half gx16[(size_t)Mrows * Dd];                 // 4 MB   [m][d]
__device__ __half gWqt16[(size_t)Hh * Dd * Dd];             // 4 MB   [h][e][d]
__device__ __half gWkt16[(size_t)Hh * Dd * Dd];
__device__ __half gWvt16[(size_t)Hh * Dd * Dd];
__device__ __half gWot16[(size_t)Dd * CONCAT_K];            // 4 MB   [e][hd]
__device__ __half gQ16[(size_t)Hh * Mrows * Dd];            // 32 MB  [h][m][e]
__device__ __half gK16[(size_t)Hh * Mrows * Dd];            // 32 MB
__device__ __half gV16[(size_t)Hh * Mrows * Dd];            // 32 MB  [h][m][e]
__device__ __half gVt16[(size_t)Hh * Dd * Mrows];           // 32 MB  [h][e][m]
__device__ __half gS16[(size_t)Bb * Hh * Ss * Ss];          // 128 MB [z][q][k]  scores -> (in-place) softmax P
__device__ __half gC16[(size_t)Mrows * CONCAT_K];           // 32 MB  [m][h*D+e]

// ---------------------------------------------------------------------------
// helpers
// ---------------------------------------------------------------------------
__device__ __forceinline__ uint32_t smem_u32(const void* p) {
    uint32_t a;
    asm("{ .reg .u64 t; cvta.to.shared.u64 t, %1; cvt.u32.u64 %0, t; }" : "=r"(a) : "l"(p));
    return a;
}
#define CP16(dst, src) asm volatile("cp.async.cg.shared.global [%0], [%1], 16;" :: "r"(dst), "l"(src))
#define CP_COMMIT()    asm volatile("cp.async.commit_group;" ::: "memory")
#define CP_WAIT1()     asm volatile("cp.async.wait_group 1;" ::: "memory")

__device__ __forceinline__ uint32_t lds32(uint32_t a) {
    uint32_t v;
    asm volatile("ld.shared.b32 %0, [%1];" : "=r"(v) : "r"(a));
    return v;
}

__device__ __forceinline__ void mma16816(float* c, const uint32_t* a, const uint32_t* b) {
    asm volatile(
        "mma.sync.aligned.m16n8k16.row.col.f32.f16.f16.f32 "
        "{%0,%1,%2,%3},{%4,%5,%6,%7},{%8,%9},{%0,%1,%2,%3};\n"
        : "+f"(c[0]), "+f"(c[1]), "+f"(c[2]), "+f"(c[3])
        : "r"(a[0]), "r"(a[1]), "r"(a[2]), "r"(a[3]), "r"(b[0]), "r"(b[1]));
}

// ---------------------------------------------------------------------------
// fp16 GEMM: C = alpha * A @ B^T (+ bias) (+ resid)   [exact round-8 kernel]
// A: [M,K] fp16 K-major (lda halves), B: [N,K] fp16 K-major (ldb halves).
// CTA tile 128x128, K-chunk 32, 3-stage cp.async pipeline, 256 threads,
// 8 warps (2x4), warp tile 64x32, mma m16n8k16, scalar-LDS fragments.
//
// MODE: 0 = merged QKV proj (z = which*8+h, half out),
//       1 = QK^T (z=b*8+h, HALF out, alpha),
//       2 = P@V (z=b*8+h, half out into concat),
//       3 = out proj (f32 + bias + resid)
// ---------------------------------------------------------------------------
#define ROW_B 80u
#define A_ST_BYTES (128u * ROW_B)        // 10240
#define STAGE_BYTES (2u * A_ST_BYTES)    // 20480
#define HG_SMEM (3 * 20480)              // 61440

template <int MODE>
__global__ __launch_bounds__(256)
void hgemm(const __half* __restrict__ A0, const __half* __restrict__ B0,
           const __half* __restrict__ B1v, const __half* __restrict__ B2v,
           void* __restrict__ C0, void* __restrict__ C1v, void* __restrict__ C2v,
           const float* __restrict__ bias0, const float* __restrict__ bias1,
           const float* __restrict__ bias2, const float* __restrict__ resid0,
           int K, int lda, int ldb, int ldc, float alpha)
{
    extern __shared__ char sm[];
    const uint32_t sbase = smem_u32(sm);

    const int tid = threadIdx.x;
    const int lane = tid & 31;
    const int wid = tid >> 5;
    const int g = lane >> 2;
    const int tig = lane & 3;
    const int warp_m = wid >> 2;   // 0..1
    const int warp_n = wid & 3;    // 0..3
    const int bx = blockIdx.x, by = blockIdx.y;

    const __half* A = A0;
    const __half* B = B0;
    const float* bias = bias0;
    float* Cf = (float*)C0;
    __half* Ch = (__half*)C0;
    {
        const int z = blockIdx.z;
        if (MODE == 0) {
            const int which = z >> 3, h = z & 7;
            const __half* W = (which == 0) ? B0 : ((which == 1) ? B1v : B2v);
            B = W + (size_t)h * Dd * Dd;
            __half* Co = (__half*)((which == 0) ? C0 : ((which == 1) ? C1v : C2v));
            Ch = Co + (size_t)h * Mrows * Dd;
            const float* bs = (which == 0) ? bias0 : ((which == 1) ? bias1 : bias2);
            bias = bs + (size_t)h * Dd;
        } else if (MODE == 1) {
            const int h = z & 7, b = z >> 3;
            const size_t off = ((size_t)h * Mrows + (size_t)b * Ss) * Dd;
            A += off; B += off;
            Ch += (size_t)z * Ss * Ss;
        } else if (MODE == 2) {
            const int h = z & 7, b = z >> 3;
            A += (size_t)z * Ss * Ss;
            B += (size_t)h * Dd * Mrows + (size_t)b * Ss;
            Ch += (size_t)b * Ss * CONCAT_K + (size_t)h * Dd;
        }
    }

    const __half* Arow = A + (size_t)(by * 128) * lda;
    const __half* Brow = B + (size_t)(bx * 128) * ldb;

    const int r0l = tid >> 2, r1l = (tid + 256) >> 2;
    const int f0l = tid & 3,  f1l = (tid + 256) & 3;

    auto issue = [&](int c, int st) {
        const __half* Ac = Arow + c * 32;
        const __half* Bc = Brow + c * 32;
        const uint32_t sA = sbase + (uint32_t)st * STAGE_BYTES;
        const uint32_t sB = sA + A_ST_BYTES;
        CP16(sA + (uint32_t)r0l * ROW_B + f0l * 16, Ac + (size_t)r0l * lda + f0l * 8);
        CP16(sB + (uint32_t)r0l * ROW_B + f0l * 16, Bc + (size_t)r0l * ldb + f0l * 8);
        CP16(sA + (uint32_t)r1l * ROW_B + f1l * 16, Ac + (size_t)r1l * lda + f1l * 8);
        CP16(sB + (uint32_t)r1l * ROW_B + f1l * 16, Bc + (size_t)r1l * ldb + f1l * 8);
    };

    float acc[4][4][4];
#pragma unroll
    for (int mi = 0; mi < 4; mi++)
#pragma unroll
        for (int ni = 0; ni < 4; ni++)
#pragma unroll
            for (int r = 0; r < 4; r++) acc[mi][ni][r] = 0.0f;

    const int nchunks = K >> 5;

    issue(0, 0); CP_COMMIT();
    issue(1, 1); CP_COMMIT();

    for (int c = 0; c < nchunks; c++) {
        CP_WAIT1();
        __syncthreads();

        const int st = c % 3;
        const uint32_t baseA = sbase + (uint32_t)st * STAGE_BYTES;
        const uint32_t baseB = baseA + A_ST_BYTES;
#pragma unroll
        for (int ks = 0; ks < 2; ks++) {
            const uint32_t kb = (uint32_t)(ks * 8 + tig) * 4;
            uint32_t a[4][4], b[4][2];
#pragma unroll
            for (int mi = 0; mi < 4; mi++) {
                const uint32_t ra = baseA + (uint32_t)(warp_m * 64 + mi * 16 + g) * ROW_B + kb;
                a[mi][0] = lds32(ra);
                a[mi][1] = lds32(ra + 8 * ROW_B);
                a[mi][2] = lds32(ra + 16);
                a[mi][3] = lds32(ra + 8 * ROW_B + 16);
            }
#pragma unroll
            for (int ni = 0; ni < 4; ni++) {
                const uint32_t rb = baseB + (uint32_t)(warp_n * 32 + ni * 8 + g) * ROW_B + kb;
                b[ni][0] = lds32(rb);
                b[ni][1] = lds32(rb + 16);
            }
#pragma unroll
            for (int mi = 0; mi < 4; mi++)
#pragma unroll
                for (int ni = 0; ni < 4; ni++)
                    mma16816(acc[mi][ni], a[mi], b[ni]);
        }

        if (c + 2 < nchunks) issue(c + 2, (c + 2) % 3);
        CP_COMMIT();
    }

    // epilogue
#pragma unroll
    for (int mi = 0; mi < 4; mi++) {
        const int row0 = by * 128 + warp_m * 64 + mi * 16 + g;
#pragma unroll
        for (int ni = 0; ni < 4; ni++) {
            const int col = bx * 128 + warp_n * 32 + ni * 8 + 2 * tig;
            float2 v0, v1;
            v0.x = acc[mi][ni][0] * alpha; v0.y = acc[mi][ni][1] * alpha;
            v1.x = acc[mi][ni][2] * alpha; v1.y = acc[mi][ni][3] * alpha;
            if (MODE == 0 || MODE == 3) {
                const float b0 = bias[col], b1 = bias[col + 1];
                v0.x += b0; v0.y += b1;
                v1.x += b0; v1.y += b1;
            }
            if (MODE == 3) {
                const float2 r0 = *(const float2*)&resid0[(size_t)row0 * ldc + col];
                const float2 r1 = *(const float2*)&resid0[(size_t)(row0 + 8) * ldc + col];
                v0.x += r0.x; v0.y += r0.y;
                v1.x += r1.x; v1.y += r1.y;
            }
            if (MODE == 3) {
                *(float2*)&Cf[(size_t)row0 * ldc + col] = v0;
                *(float2*)&Cf[(size_t)(row0 + 8) * ldc + col] = v1;
            } else {
                *(__half2*)&Ch[(size_t)row0 * ldc + col] = __floats2half2_rn(v0.x, v0.y);
                *(__half2*)&Ch[(size_t)(row0 + 8) * ldc + col] = __floats2half2_rn(v1.x, v1.y);
            }
        }
    }
}

// ---------------------------------------------------------------------------
// fp32 -> fp16 elementwise (float4 granularity)
// ---------------------------------------------------------------------------
__global__ __launch_bounds__(256)
void cvt_half(const float* __restrict__ in, __half* __restrict__ out)
{
    const size_t i = (size_t)blockIdx.x * 256 + threadIdx.x;
    const float4 v = ((const float4*)in)[i];
    ((__half2*)out)[2 * i]     = __floats2half2_rn(v.x, v.y);
    ((__half2*)out)[2 * i + 1] = __floats2half2_rn(v.z, v.w);
}

// ---------------------------------------------------------------------------
// merged fp32 [z][512][512] -> fp16 transposed, 3 weight tensors (z = which*8+h)
// ---------------------------------------------------------------------------
__global__ __launch_bounds__(256)
void cvtT3(const float* __restrict__ q, const float* __restrict__ k,
           const float* __restrict__ v,
           __half* __restrict__ qo, __half* __restrict__ ko, __half* __restrict__ vo)
{
    __shared__ float t[32][33];
    const int which = blockIdx.z >> 3, h = blockIdx.z & 7;
    const float* in = ((which == 0) ? q : (which == 1) ? k : v) + (size_t)h * Dd * Dd;
    __half* out = ((which == 0) ? qo : (which == 1) ? ko : vo) + (size_t)h * Dd * Dd;
    const int c0 = blockIdx.x * 32, r0 = blockIdx.y * 32;
    const int tx = threadIdx.x & 31, ty = threadIdx.x >> 5;
#pragma unroll
    for (int i = 0; i < 32; i += 8)
        t[ty + i][tx] = in[(size_t)(r0 + ty + i) * Dd + c0 + tx];
    __syncthreads();
#pragma unroll
    for (int i = 0; i < 32; i += 8)
        out[(size_t)(c0 + ty + i) * Dd + r0 + tx] = __float2half(t[tx][ty + i]);
}

// ---------------------------------------------------------------------------
// fp32 [z][R][C] -> fp16 transposed [z][C][R]
// ---------------------------------------------------------------------------
__global__ __launch_bounds__(256)
void cvtT(const float* __restrict__ in, __half* __restrict__ out, int R, int C)
{
    __shared__ float t[32][33];
    in  += (size_t)blockIdx.z * R * C;
    out += (size_t)blockIdx.z * R * C;
    const int c0 = blockIdx.x * 32, r0 = blockIdx.y * 32;
    const int tx = threadIdx.x & 31, ty = threadIdx.x >> 5;
#pragma unroll
    for (int i = 0; i < 32; i += 8)
        t[ty + i][tx] = in[(size_t)(r0 + ty + i) * C + c0 + tx];
    __syncthreads();
#pragma unroll
    for (int i = 0; i < 32; i += 8)
        out[(size_t)(c0 + ty + i) * R + r0 + tx] = __float2half(t[tx][ty + i]);
}

// ---------------------------------------------------------------------------
// fp16 [z][R][C] -> fp16 transposed [z][C][R]
// ---------------------------------------------------------------------------
__global__ __launch_bounds__(256)
void transpose16(const __half* __restrict__ in, __half* __restrict__ out, int R, int C)
{
    __shared__ __half t[32][34];
    in  += (size_t)blockIdx.z * R * C;
    out += (size_t)blockIdx.z * R * C;
    const int c0 = blockIdx.x * 32, r0 = blockIdx.y * 32;
    const int tx = threadIdx.x & 31, ty = threadIdx.x >> 5;
#pragma unroll
    for (int i = 0; i < 32; i += 8)
        t[ty + i][tx] = in[(size_t)(r0 + ty + i) * C + c0 + tx];
    __syncthreads();
#pragma unroll
    for (int i = 0; i < 32; i += 8)
        out[(size_t)(c0 + ty + i) * R + r0 + tx] = t[tx][ty + i];
}

// ---------------------------------------------------------------------------
// Row softmax, fp16 in-place, warp-shuffle reductions (2 barriers total).
// One block per row of 2048; 256 threads x 8 halves.
// ---------------------------------------------------------------------------
__global__ __launch_bounds__(256)
void softmax16_kernel(__half* __restrict__ S)
{
    __shared__ float red[8];
    __half* p = S + (size_t)blockIdx.x * Ss;
    const int t = threadIdx.x;
    const int lane = t & 31, w = t >> 5;

    uint4 raw = ((const uint4*)p)[t];
    const __half2* hp = (const __half2*)&raw;
    float2 f[4];
#pragma unroll
    for (int i = 0; i < 4; i++) f[i] = __half22float2(hp[i]);

    float m = f[0].x;
#pragma unroll
    for (int i = 0; i < 4; i++) m = fmaxf(m, fmaxf(f[i].x, f[i].y));
#pragma unroll
    for (int s = 16; s > 0; s >>= 1)
        m = fmaxf(m, __shfl_xor_sync(0xFFFFFFFFu, m, s));
    if (lane == 0) red[w] = m;
    __syncthreads();
    {
        float mm = red[lane & 7];
#pragma unroll
        for (int s = 4; s > 0; s >>= 1)
            mm = fmaxf(mm, __shfl_xor_sync(0xFFFFFFFFu, mm, s));
        m = mm;
    }

    float sum = 0.0f;
#pragma unroll
    for (int i = 0; i < 4; i++) {
        f[i].x = __expf(f[i].x - m); f[i].y = __expf(f[i].y - m);
        sum += f[i].x + f[i].y;
    }
#pragma unroll
    for (int s = 16; s > 0; s >>= 1)
        sum += __shfl_xor_sync(0xFFFFFFFFu, sum, s);
    if (lane == 0) red[w] = sum;
    __syncthreads();
    {
        float ss = red[lane & 7];
#pragma unroll
        for (int s = 4; s > 0; s >>= 1)
            ss += __shfl_xor_sync(0xFFFFFFFFu, ss, s);
        sum = ss;
    }
    const float inv = 1.0f / sum;

    uint4 outw;
    __half2* op = (__half2*)&outw;
#pragma unroll
    for (int i = 0; i < 4; i++)
        op[i] = __floats2half2_rn(f[i].x * inv, f[i].y * inv);
    ((uint4*)p)[t] = outw;
}

// ---------------------------------------------------------------------------
extern "C" void kernel_launch(void* const* d_in, const int* in_sizes, int n_in,
                              void* d_out, int out_size)
{
    const float* x  = (const float*)d_in[0];
    const float* Wq = (const float*)d_in[1];
    const float* Wk = (const float*)d_in[2];
    const float* Wv = (const float*)d_in[3];
    const float* bq = (const float*)d_in[4];
    const float* bk = (const float*)d_in[5];
    const float* bv = (const float*)d_in[6];
    const float* Wo = (const float*)d_in[7];
    const float* bo = (const float*)d_in[8];
    float* out = (float*)d_out;

    __half *px16, *pWqt, *pWkt, *pWvt, *pWot, *pQ, *pK, *pV, *pVt, *pS, *pC;
    cudaGetSymbolAddress((void**)&px16, gx16);
    cudaGetSymbolAddress((void**)&pWqt, gWqt16);
    cudaGetSymbolAddress((void**)&pWkt, gWkt16);
    cudaGetSymbolAddress((void**)&pWvt, gWvt16);
    cudaGetSymbolAddress((void**)&pWot, gWot16);
    cudaGetSymbolAddress((void**)&pQ, gQ16);
    cudaGetSymbolAddress((void**)&pK, gK16);
    cudaGetSymbolAddress((void**)&pV, gV16);
    cudaGetSymbolAddress((void**)&pVt, gVt16);
    cudaGetSymbolAddress((void**)&pS, gS16);
    cudaGetSymbolAddress((void**)&pC, gC16);

    cudaFuncSetAttribute((const void*)hgemm<0>, cudaFuncAttributeMaxDynamicSharedMemorySize, HG_SMEM);
    cudaFuncSetAttribute((const void*)hgemm<1>, cudaFuncAttributeMaxDynamicSharedMemorySize, HG_SMEM);
    cudaFuncSetAttribute((const void*)hgemm<2>, cudaFuncAttributeMaxDynamicSharedMemorySize, HG_SMEM);
    cudaFuncSetAttribute((const void*)hgemm<3>, cudaFuncAttributeMaxDynamicSharedMemorySize, HG_SMEM);

    const float scale = 0.044194173824159216f;  // 1/sqrt(512)
    const dim3 blk(256);

    // 0) convert inputs to fp16 K-major operands
    cvt_half<<<Mrows * Dd / 1024, blk>>>(x, px16);
    cvtT3<<<dim3(16, 16, 24), blk>>>(Wq, Wk, Wv, pWqt, pWkt, pWvt);
    cvtT<<<dim3(16, 128, 1), blk>>>(Wo, pWot, CONCAT_K, Dd);

    // 1) merged QKV projections: [4096,512] = x16 @ W^T(h) per (which, h)
    hgemm<0><<<dim3(4, 32, 24), blk, HG_SMEM>>>(px16, pWqt, pWkt, pWvt,
                                                pQ, pK, pV, bq, bk, bv, nullptr,
                                                Dd, Dd, Dd, Dd, 1.0f);

    // 1b) V -> transposed [h][e][m]
    transpose16<<<dim3(16, 128, Hh), blk>>>(pV, pVt, Mrows, Dd);

    // 2) scores = scale * Q @ K^T, fp16 out
    hgemm<1><<<dim3(16, 16, Bb * Hh), blk, HG_SMEM>>>(pQ, pK, nullptr, nullptr,
                                                      pS, nullptr, nullptr,
                                                      nullptr, nullptr, nullptr, nullptr,
                                                      Dd, Dd, Dd, Ss, scale);

    // 3) softmax in place (fp16)
    softmax16_kernel<<<Bb * Hh * Ss, 256>>>(pS);

    // 4) O = P @ V -> fp16 concat layout [m][h*512+e]
    hgemm<2><<<dim3(4, 16, Bb * Hh), blk, HG_SMEM>>>(pS, pVt, nullptr, nullptr,
                                                     pC, nullptr, nullptr,
                                                     nullptr, nullptr, nullptr, nullptr,
                                                     Ss, Ss, Mrows, CONCAT_K, 1.0f);

    // 5) out = concat @ Wo^T + bo + x, fp32
    hgemm<3><<<dim3(4, 32, 1), blk, HG_SMEM>>>(pC, pWot, nullptr, nullptr,
                                               out, nullptr, nullptr,
                                               bo, nullptr, nullptr, x,
                                               CONCAT_K, CONCAT_K, CONCAT_K, Dd, 1.0f);
}

// round 13
// speedup vs baseline: 1.7413x; 1.0151x over previous
#include <cuda_runtime.h>
#include <cuda_fp16.h>
#include <math.h>
#include <stdint.h>

// Problem constants
#define Bb 2
#define Hh 8
#define Ss 2048
#define Dd 512
#define Mrows (Bb * Ss)          // 4096
#define CONCAT_K (Hh * Dd)       // 4096
#define KSPLIT 4
#define KSPLIT_LEN (CONCAT_K / KSPLIT)   // 1024

// ---------------------------------------------------------------------------
// Scratch (device globals; allocation is forbidden)
// ---------------------------------------------------------------------------
__device__ __half gx16[(size_t)Mrows * Dd];                 // 4 MB   [m][d]
__device__ __half gWqt16[(size_t)Hh * Dd * Dd];             // 4 MB   [h][e][d]
__device__ __half gWkt16[(size_t)Hh * Dd * Dd];
__device__ __half gWvt16[(size_t)Hh * Dd * Dd];
__device__ __half gWot16[(size_t)Dd * CONCAT_K];            // 4 MB   [e][hd]
__device__ __half gQ16[(size_t)Hh * Mrows * Dd];            // 32 MB  [h][m][e]
__device__ __half gK16[(size_t)Hh * Mrows * Dd];            // 32 MB
__device__ __half gVt16[(size_t)Hh * Dd * Mrows];           // 32 MB  [h][e][m]
__device__ __half gS16[(size_t)Bb * Hh * Ss * Ss];          // 128 MB [z][q][k]  scores -> (in-place) softmax P
__device__ __half gC16[(size_t)Mrows * CONCAT_K];           // 32 MB  [m][h*D+e]
__device__ float  gPart[(size_t)KSPLIT * Mrows * Dd];       // 32 MB  split-K partials

// ---------------------------------------------------------------------------
// helpers
// ---------------------------------------------------------------------------
__device__ __forceinline__ uint32_t smem_u32(const void* p) {
    uint32_t a;
    asm("{ .reg .u64 t; cvta.to.shared.u64 t, %1; cvt.u32.u64 %0, t; }" : "=r"(a) : "l"(p));
    return a;
}
#define CP16(dst, src) asm volatile("cp.async.cg.shared.global [%0], [%1], 16;" :: "r"(dst), "l"(src))
#define CP_COMMIT()    asm volatile("cp.async.commit_group;" ::: "memory")
#define CP_WAIT1()     asm volatile("cp.async.wait_group 1;" ::: "memory")

__device__ __forceinline__ uint32_t lds32(uint32_t a) {
    uint32_t v;
    asm volatile("ld.shared.b32 %0, [%1];" : "=r"(v) : "r"(a));
    return v;
}

__device__ __forceinline__ void mma16816(float* c, const uint32_t* a, const uint32_t* b) {
    asm volatile(
        "mma.sync.aligned.m16n8k16.row.col.f32.f16.f16.f32 "
        "{%0,%1,%2,%3},{%4,%5,%6,%7},{%8,%9},{%0,%1,%2,%3};\n"
        : "+f"(c[0]), "+f"(c[1]), "+f"(c[2]), "+f"(c[3])
        : "r"(a[0]), "r"(a[1]), "r"(a[2]), "r"(a[3]), "r"(b[0]), "r"(b[1]));
}

// ---------------------------------------------------------------------------
// fp16 GEMM: C = alpha * A @ B^T (+ bias) (+ resid)   [frozen round-8 core]
// A: [M,K] fp16 K-major (lda halves), B: [N,K] fp16 K-major (ldb halves).
// CTA tile 128x128, K-chunk 32, 3-stage cp.async pipeline, 256 threads,
// 8 warps (2x4), warp tile 64x32, mma m16n8k16, scalar-LDS fragments.
//
// MODE: 0 = merged Q/K proj (z = which*8+h, half out, col bias),
//       1 = QK^T (z=b*8+h, half out, alpha),
//       2 = P@V (z=b*8+h, half out into concat),
//       4 = V^T proj (z=h, A=Wvt_h, B=x16, half out, ROW bias),
//       5 = split-K out-proj partial (z=ksplit, fp32 out, no bias)
// ---------------------------------------------------------------------------
#define ROW_B 80u
#define A_ST_BYTES (128u * ROW_B)        // 10240
#define STAGE_BYTES (2u * A_ST_BYTES)    // 20480
#define HG_SMEM (3 * 20480)              // 61440

template <int MODE>
__global__ __launch_bounds__(256)
void hgemm(const __half* __restrict__ A0, const __half* __restrict__ B0,
           const __half* __restrict__ B1v, const __half* __restrict__ B2v,
           void* __restrict__ C0, void* __restrict__ C1v, void* __restrict__ C2v,
           const float* __restrict__ bias0, const float* __restrict__ bias1,
           const float* __restrict__ bias2, const float* __restrict__ resid0,
           int K, int lda, int ldb, int ldc, float alpha)
{
    extern __shared__ char sm[];
    const uint32_t sbase = smem_u32(sm);

    const int tid = threadIdx.x;
    const int lane = tid & 31;
    const int wid = tid >> 5;
    const int g = lane >> 2;
    const int tig = lane & 3;
    const int warp_m = wid >> 2;   // 0..1
    const int warp_n = wid & 3;    // 0..3
    const int bx = blockIdx.x, by = blockIdx.y;

    const __half* A = A0;
    const __half* B = B0;
    const float* bias = bias0;
    float* Cf = (float*)C0;
    __half* Ch = (__half*)C0;
    {
        const int z = blockIdx.z;
        if (MODE == 0) {
            const int which = z >> 3, h = z & 7;
            const __half* W = (which == 0) ? B0 : B1v;
            B = W + (size_t)h * Dd * Dd;
            __half* Co = (__half*)((which == 0) ? C0 : C1v);
            Ch = Co + (size_t)h * Mrows * Dd;
            const float* bs = (which == 0) ? bias0 : bias1;
            bias = bs + (size_t)h * Dd;
        } else if (MODE == 1) {
            const int h = z & 7, b = z >> 3;
            const size_t off = ((size_t)h * Mrows + (size_t)b * Ss) * Dd;
            A += off; B += off;
            Ch += (size_t)z * Ss * Ss;
        } else if (MODE == 2) {
            const int h = z & 7, b = z >> 3;
            A += (size_t)z * Ss * Ss;
            B += (size_t)h * Dd * Mrows + (size_t)b * Ss;
            Ch += (size_t)b * Ss * CONCAT_K + (size_t)h * Dd;
        } else if (MODE == 4) {
            A += (size_t)z * Dd * Dd;          // Wvt for head z
            Ch += (size_t)z * Dd * Mrows;      // Vt slab for head z
            bias = bias0 + (size_t)z * Dd;     // bv[h], indexed by ROW
        } else if (MODE == 5) {
            A += (size_t)z * KSPLIT_LEN;       // K-window in concat
            B += (size_t)z * KSPLIT_LEN;
            Cf += (size_t)z * Mrows * Dd;      // partial buffer slab
        }
    }

    const __half* Arow = A + (size_t)(by * 128) * lda;
    const __half* Brow = B + (size_t)(bx * 128) * ldb;

    const int r0l = tid >> 2, r1l = (tid + 256) >> 2;
    const int f0l = tid & 3,  f1l = (tid + 256) & 3;

    auto issue = [&](int c, int st) {
        const __half* Ac = Arow + c * 32;
        const __half* Bc = Brow + c * 32;
        const uint32_t sA = sbase + (uint32_t)st * STAGE_BYTES;
        const uint32_t sB = sA + A_ST_BYTES;
        CP16(sA + (uint32_t)r0l * ROW_B + f0l * 16, Ac + (size_t)r0l * lda + f0l * 8);
        CP16(sB + (uint32_t)r0l * ROW_B + f0l * 16, Bc + (size_t)r0l * ldb + f0l * 8);
        CP16(sA + (uint32_t)r1l * ROW_B + f1l * 16, Ac + (size_t)r1l * lda + f1l * 8);
        CP16(sB + (uint32_t)r1l * ROW_B + f1l * 16, Bc + (size_t)r1l * ldb + f1l * 8);
    };

    float acc[4][4][4];
#pragma unroll
    for (int mi = 0; mi < 4; mi++)
#pragma unroll
        for (int ni = 0; ni < 4; ni++)
#pragma unroll
            for (int r = 0; r < 4; r++) acc[mi][ni][r] = 0.0f;

    const int nchunks = K >> 5;

    issue(0, 0); CP_COMMIT();
    issue(1, 1); CP_COMMIT();

    for (int c = 0; c < nchunks; c++) {
        CP_WAIT1();
        __syncthreads();

        const int st = c % 3;
        const uint32_t baseA = sbase + (uint32_t)st * STAGE_BYTES;
        const uint32_t baseB = baseA + A_ST_BYTES;
#pragma unroll
        for (int ks = 0; ks < 2; ks++) {
            const uint32_t kb = (uint32_t)(ks * 8 + tig) * 4;
            uint32_t a[4][4], b[4][2];
#pragma unroll
            for (int mi = 0; mi < 4; mi++) {
                const uint32_t ra = baseA + (uint32_t)(warp_m * 64 + mi * 16 + g) * ROW_B + kb;
                a[mi][0] = lds32(ra);
                a[mi][1] = lds32(ra + 8 * ROW_B);
                a[mi][2] = lds32(ra + 16);
                a[mi][3] = lds32(ra + 8 * ROW_B + 16);
            }
#pragma unroll
            for (int ni = 0; ni < 4; ni++) {
                const uint32_t rb = baseB + (uint32_t)(warp_n * 32 + ni * 8 + g) * ROW_B + kb;
                b[ni][0] = lds32(rb);
                b[ni][1] = lds32(rb + 16);
            }
#pragma unroll
            for (int mi = 0; mi < 4; mi++)
#pragma unroll
                for (int ni = 0; ni < 4; ni++)
                    mma16816(acc[mi][ni], a[mi], b[ni]);
        }

        if (c + 2 < nchunks) issue(c + 2, (c + 2) % 3);
        CP_COMMIT();
    }

    // epilogue
#pragma unroll
    for (int mi = 0; mi < 4; mi++) {
        const int row0 = by * 128 + warp_m * 64 + mi * 16 + g;
#pragma unroll
        for (int ni = 0; ni < 4; ni++) {
            const int col = bx * 128 + warp_n * 32 + ni * 8 + 2 * tig;
            float2 v0, v1;
            v0.x = acc[mi][ni][0] * alpha; v0.y = acc[mi][ni][1] * alpha;
            v1.x = acc[mi][ni][2] * alpha; v1.y = acc[mi][ni][3] * alpha;
            if (MODE == 0) {
                const float b0 = bias[col], b1 = bias[col + 1];
                v0.x += b0; v0.y += b1;
                v1.x += b0; v1.y += b1;
            }
            if (MODE == 4) {
                const float br0 = bias[row0], br1 = bias[row0 + 8];   // row bias
                v0.x += br0; v0.y += br0;
                v1.x += br1; v1.y += br1;
            }
            if (MODE == 5) {
                *(float2*)&Cf[(size_t)row0 * ldc + col] = v0;
                *(float2*)&Cf[(size_t)(row0 + 8) * ldc + col] = v1;
            } else {
                *(__half2*)&Ch[(size_t)row0 * ldc + col] = __floats2half2_rn(v0.x, v0.y);
                *(__half2*)&Ch[(size_t)(row0 + 8) * ldc + col] = __floats2half2_rn(v1.x, v1.y);
            }
        }
    }
}

// ---------------------------------------------------------------------------
// split-K reduce: out = p0+p1+p2+p3 + bo[col] + x   (float4 granularity)
// ---------------------------------------------------------------------------
__global__ __launch_bounds__(256)
void reduce_out(const float* __restrict__ part, const float* __restrict__ x,
                const float* __restrict__ bo, float* __restrict__ out)
{
    const size_t i = (size_t)blockIdx.x * 256 + threadIdx.x;   // float4 idx over 2M/4
    const size_t off = (size_t)Mrows * Dd / 4;
    float4 s = ((const float4*)part)[i];
    const float4 p1 = ((const float4*)part)[i + off];
    const float4 p2 = ((const float4*)part)[i + 2 * off];
    const float4 p3 = ((const float4*)part)[i + 3 * off];
    const float4 xv = ((const float4*)x)[i];
    const float4 bv = ((const float4*)bo)[i & 127];            // 512 floats = 128 float4 per row
    s.x += p1.x + p2.x + p3.x + xv.x + bv.x;
    s.y += p1.y + p2.y + p3.y + xv.y + bv.y;
    s.z += p1.z + p2.z + p3.z + xv.z + bv.z;
    s.w += p1.w + p2.w + p3.w + xv.w + bv.w;
    ((float4*)out)[i] = s;
}

// ---------------------------------------------------------------------------
// fp32 -> fp16 elementwise (float4 granularity)
// ---------------------------------------------------------------------------
__global__ __launch_bounds__(256)
void cvt_half(const float* __restrict__ in, __half* __restrict__ out)
{
    const size_t i = (size_t)blockIdx.x * 256 + threadIdx.x;
    const float4 v = ((const float4*)in)[i];
    ((__half2*)out)[2 * i]     = __floats2half2_rn(v.x, v.y);
    ((__half2*)out)[2 * i + 1] = __floats2half2_rn(v.z, v.w);
}

// ---------------------------------------------------------------------------
// merged fp32 [z][512][512] -> fp16 transposed, 3 weight tensors (z = which*8+h)
// ---------------------------------------------------------------------------
__global__ __launch_bounds__(256)
void cvtT3(const float* __restrict__ q, const float* __restrict__ k,
           const float* __restrict__ v,
           __half* __restrict__ qo, __half* __restrict__ ko, __half* __restrict__ vo)
{
    __shared__ float t[32][33];
    const int which = blockIdx.z >> 3, h = blockIdx.z & 7;
    const float* in = ((which == 0) ? q : (which == 1) ? k : v) + (size_t)h * Dd * Dd;
    __half* out = ((which == 0) ? qo : (which == 1) ? ko : vo) + (size_t)h * Dd * Dd;
    const int c0 = blockIdx.x * 32, r0 = blockIdx.y * 32;
    const int tx = threadIdx.x & 31, ty = threadIdx.x >> 5;
#pragma unroll
    for (int i = 0; i < 32; i += 8)
        t[ty + i][tx] = in[(size_t)(r0 + ty + i) * Dd + c0 + tx];
    __syncthreads();
#pragma unroll
    for (int i = 0; i < 32; i += 8)
        out[(size_t)(c0 + ty + i) * Dd + r0 + tx] = __float2half(t[tx][ty + i]);
}

// ---------------------------------------------------------------------------
// fp32 [z][R][C] -> fp16 transposed [z][C][R]
// ---------------------------------------------------------------------------
__global__ __launch_bounds__(256)
void cvtT(const float* __restrict__ in, __half* __restrict__ out, int R, int C)
{
    __shared__ float t[32][33];
    in  += (size_t)blockIdx.z * R * C;
    out += (size_t)blockIdx.z * R * C;
    const int c0 = blockIdx.x * 32, r0 = blockIdx.y * 32;
    const int tx = threadIdx.x & 31, ty = threadIdx.x >> 5;
#pragma unroll
    for (int i = 0; i < 32; i += 8)
        t[ty + i][tx] = in[(size_t)(r0 + ty + i) * C + c0 + tx];
    __syncthreads();
#pragma unroll
    for (int i = 0; i < 32; i += 8)
        out[(size_t)(c0 + ty + i) * R + r0 + tx] = __float2half(t[tx][ty + i]);
}

// ---------------------------------------------------------------------------
// Row softmax, fp16 in-place, warp-shuffle reductions (2 barriers total).
// ---------------------------------------------------------------------------
__global__ __launch_bounds__(256)
void softmax16_kernel(__half* __restrict__ S)
{
    __shared__ float red[8];
    __half* p = S + (size_t)blockIdx.x * Ss;
    const int t = threadIdx.x;
    const int lane = t & 31, w = t >> 5;

    uint4 raw = ((const uint4*)p)[t];
    const __half2* hp = (const __half2*)&raw;
    float2 f[4];
#pragma unroll
    for (int i = 0; i < 4; i++) f[i] = __half22float2(hp[i]);

    float m = f[0].x;
#pragma unroll
    for (int i = 0; i < 4; i++) m = fmaxf(m, fmaxf(f[i].x, f[i].y));
#pragma unroll
    for (int s = 16; s > 0; s >>= 1)
        m = fmaxf(m, __shfl_xor_sync(0xFFFFFFFFu, m, s));
    if (lane == 0) red[w] = m;
    __syncthreads();
    {
        float mm = red[lane & 7];
#pragma unroll
        for (int s = 4; s > 0; s >>= 1)
            mm = fmaxf(mm, __shfl_xor_sync(0xFFFFFFFFu, mm, s));
        m = mm;
    }

    float sum = 0.0f;
#pragma unroll
    for (int i = 0; i < 4; i++) {
        f[i].x = __expf(f[i].x - m); f[i].y = __expf(f[i].y - m);
        sum += f[i].x + f[i].y;
    }
#pragma unroll
    for (int s = 16; s > 0; s >>= 1)
        sum += __shfl_xor_sync(0xFFFFFFFFu, sum, s);
    if (lane == 0) red[w] = sum;
    __syncthreads();
    {
        float ss = red[lane & 7];
#pragma unroll
        for (int s = 4; s > 0; s >>= 1)
            ss += __shfl_xor_sync(0xFFFFFFFFu, ss, s);
        sum = ss;
    }
    const float inv = 1.0f / sum;

    uint4 outw;
    __half2* op = (__half2*)&outw;
#pragma unroll
    for (int i = 0; i < 4; i++)
        op[i] = __floats2half2_rn(f[i].x * inv, f[i].y * inv);
    ((uint4*)p)[t] = outw;
}

// ---------------------------------------------------------------------------
extern "C" void kernel_launch(void* const* d_in, const int* in_sizes, int n_in,
                              void* d_out, int out_size)
{
    const float* x  = (const float*)d_in[0];
    const float* Wq = (const float*)d_in[1];
    const float* Wk = (const float*)d_in[2];
    const float* Wv = (const float*)d_in[3];
    const float* bq = (const float*)d_in[4];
    const float* bk = (const float*)d_in[5];
    const float* bv = (const float*)d_in[6];
    const float* Wo = (const float*)d_in[7];
    const float* bo = (const float*)d_in[8];
    float* out = (float*)d_out;

    __half *px16, *pWqt, *pWkt, *pWvt, *pWot, *pQ, *pK, *pVt, *pS, *pC;
    float *pPart;
    cudaGetSymbolAddress((void**)&px16, gx16);
    cudaGetSymbolAddress((void**)&pWqt, gWqt16);
    cudaGetSymbolAddress((void**)&pWkt, gWkt16);
    cudaGetSymbolAddress((void**)&pWvt, gWvt16);
    cudaGetSymbolAddress((void**)&pWot, gWot16);
    cudaGetSymbolAddress((void**)&pQ, gQ16);
    cudaGetSymbolAddress((void**)&pK, gK16);
    cudaGetSymbolAddress((void**)&pVt, gVt16);
    cudaGetSymbolAddress((void**)&pS, gS16);
    cudaGetSymbolAddress((void**)&pC, gC16);
    cudaGetSymbolAddress((void**)&pPart, gPart);

    cudaFuncSetAttribute((const void*)hgemm<0>, cudaFuncAttributeMaxDynamicSharedMemorySize, HG_SMEM);
    cudaFuncSetAttribute((const void*)hgemm<1>, cudaFuncAttributeMaxDynamicSharedMemorySize, HG_SMEM);
    cudaFuncSetAttribute((const void*)hgemm<2>, cudaFuncAttributeMaxDynamicSharedMemorySize, HG_SMEM);
    cudaFuncSetAttribute((const void*)hgemm<4>, cudaFuncAttributeMaxDynamicSharedMemorySize, HG_SMEM);
    cudaFuncSetAttribute((const void*)hgemm<5>, cudaFuncAttributeMaxDynamicSharedMemorySize, HG_SMEM);

    const float scale = 0.044194173824159216f;  // 1/sqrt(512)
    const dim3 blk(256);

    // 0) convert inputs to fp16 K-major operands
    cvt_half<<<Mrows * Dd / 1024, blk>>>(x, px16);
    cvtT3<<<dim3(16, 16, 24), blk>>>(Wq, Wk, Wv, pWqt, pWkt, pWvt);
    cvtT<<<dim3(16, 128, 1), blk>>>(Wo, pWot, CONCAT_K, Dd);

    // 1) merged Q/K projections: [4096,512] = x16 @ W^T(h)  (z = which*8+h, which in {Q,K})
    hgemm<0><<<dim3(4, 32, 16), blk, HG_SMEM>>>(px16, pWqt, pWkt, nullptr,
                                                pQ, pK, nullptr, bq, bk, nullptr, nullptr,
                                                Dd, Dd, Dd, Dd, 1.0f);

    // 1b) V^T projection, written directly transposed: Vt[h][e][m] = Wvt_h @ x16^T + bv[e]
    hgemm<4><<<dim3(32, 4, Hh), blk, HG_SMEM>>>(pWvt, px16, nullptr, nullptr,
                                                pVt, nullptr, nullptr, bv, nullptr, nullptr, nullptr,
                                                Dd, Dd, Dd, Mrows, 1.0f);

    // 2) scores = scale * Q @ K^T, fp16 out
    hgemm<1><<<dim3(16, 16, Bb * Hh), blk, HG_SMEM>>>(pQ, pK, nullptr, nullptr,
                                                      pS, nullptr, nullptr,
                                                      nullptr, nullptr, nullptr, nullptr,
                                                      Dd, Dd, Dd, Ss, scale);

    // 3) softmax in place (fp16)
    softmax16_kernel<<<Bb * Hh * Ss, 256>>>(pS);

    // 4) O = P @ V -> fp16 concat layout [m][h*512+e]
    hgemm<2><<<dim3(4, 16, Bb * Hh), blk, HG_SMEM>>>(pS, pVt, nullptr, nullptr,
                                                     pC, nullptr, nullptr,
                                                     nullptr, nullptr, nullptr, nullptr,
                                                     Ss, Ss, Mrows, CONCAT_K, 1.0f);

    // 5) out-proj split-K partials: part[z] = concat[:, z*1024:(z+1)*1024] @ Wo^T slice
    hgemm<5><<<dim3(4, 32, KSPLIT), blk, HG_SMEM>>>(pC, pWot, nullptr, nullptr,
                                                    pPart, nullptr, nullptr,
                                                    nullptr, nullptr, nullptr, nullptr,
                                                    KSPLIT_LEN, CONCAT_K, CONCAT_K, Dd, 1.0f);

    // 6) out = sum(partials) + bo + x
    reduce_out<<<Mrows * Dd / 1024, blk>>>(pPart, x, bo, out);
}